// round 2
// baseline (speedup 1.0000x reference)
#include <cuda_runtime.h>
#include <cstdint>

#define MAXN 131072
#define PAD 16   // padded row stride (floats) for Y/Z: 64B-aligned -> 2 sectors per gather

__device__ float g_Y[MAXN * PAD];
__device__ float g_Z[MAXN * PAD];

__device__ __forceinline__ float fast_tanh(float x) {
    float y;
    asm("tanh.approx.f32 %0, %1;" : "=f"(y) : "f"(x));
    return y;
}

// ---------------------------------------------------------------------------
// Kernel 1: per-node precompute of Y (src half of W) and Z (dst half of W),
// with one-hot node-type bias folded in.
//   Y[n][o] = sum_d x[n][d]*W[o][d]    + W[o][64 + t[n]]
//   Z[n][o] = sum_d x[n][d]*W[o][32+d] + W[o][68 + t[n]]
// One thread per node; x row = exactly one 128B line per thread.
// ---------------------------------------------------------------------------
__global__ void node_precompute(const float* __restrict__ x,
                                const int* __restrict__ node_types,
                                const float* __restrict__ W,
                                int N) {
    __shared__ float sW[9 * 72];
    for (int i = threadIdx.x; i < 9 * 72; i += blockDim.x) sW[i] = W[i];
    __syncthreads();

    int n = blockIdx.x * blockDim.x + threadIdx.x;
    if (n >= N) return;

    // Load this node's x row (32 floats = 128B, line-aligned)
    float xr[32];
    const float4* xp = reinterpret_cast<const float4*>(x + (size_t)n * 32);
#pragma unroll
    for (int i = 0; i < 8; i++) {
        float4 v = xp[i];
        xr[4 * i + 0] = v.x; xr[4 * i + 1] = v.y;
        xr[4 * i + 2] = v.z; xr[4 * i + 3] = v.w;
    }

    int t = node_types[n];

    float* Yp = g_Y + (size_t)n * PAD;
    float* Zp = g_Z + (size_t)n * PAD;

    float yv[9], zv[9];
#pragma unroll
    for (int o = 0; o < 9; o++) {
        const float* wrow = sW + o * 72;
        float accY = wrow[64 + t];
        float accZ = wrow[68 + t];
#pragma unroll
        for (int d = 0; d < 32; d++) {
            accY = fmaf(xr[d], wrow[d],      accY);
            accZ = fmaf(xr[d], wrow[32 + d], accZ);
        }
        yv[o] = accY;
        zv[o] = accZ;
    }

    // 64B-aligned vector stores
    reinterpret_cast<float4*>(Yp)[0] = make_float4(yv[0], yv[1], yv[2], yv[3]);
    reinterpret_cast<float4*>(Yp)[1] = make_float4(yv[4], yv[5], yv[6], yv[7]);
    Yp[8] = yv[8];
    reinterpret_cast<float4*>(Zp)[0] = make_float4(zv[0], zv[1], zv[2], zv[3]);
    reinterpret_cast<float4*>(Zp)[1] = make_float4(zv[4], zv[5], zv[6], zv[7]);
    Zp[8] = zv[8];
}

// ---------------------------------------------------------------------------
// Kernel 2: per-edge: out[e][o] = tanh(Y[src][o] + Z[dst][o])
// Gathers are 2x (float4,float4,float) = 36B from 64B-aligned rows (2 sectors).
// Output staged through smem for fully coalesced stores.
// ---------------------------------------------------------------------------
__global__ void edge_kernel(const int* __restrict__ ei,
                            float* __restrict__ out,
                            int E) {
    __shared__ float sbuf[256 * 9];

    int e = blockIdx.x * 256 + threadIdx.x;

    float r[9];
    if (e < E) {
        int s = ei[e];
        int d = ei[E + e];

        const float4* Y4 = reinterpret_cast<const float4*>(g_Y + (size_t)s * PAD);
        const float4* Z4 = reinterpret_cast<const float4*>(g_Z + (size_t)d * PAD);
        float4 ya = Y4[0], yb = Y4[1];
        float  yc = g_Y[(size_t)s * PAD + 8];
        float4 za = Z4[0], zb = Z4[1];
        float  zc = g_Z[(size_t)d * PAD + 8];

        r[0] = fast_tanh(ya.x + za.x);
        r[1] = fast_tanh(ya.y + za.y);
        r[2] = fast_tanh(ya.z + za.z);
        r[3] = fast_tanh(ya.w + za.w);
        r[4] = fast_tanh(yb.x + zb.x);
        r[5] = fast_tanh(yb.y + zb.y);
        r[6] = fast_tanh(yb.z + zb.z);
        r[7] = fast_tanh(yb.w + zb.w);
        r[8] = fast_tanh(yc + zc);
    } else {
#pragma unroll
        for (int o = 0; o < 9; o++) r[o] = 0.0f;
    }

    // stage: stride 9 across threads -> 9 coprime to 32 -> conflict-free
#pragma unroll
    for (int o = 0; o < 9; o++) sbuf[threadIdx.x * 9 + o] = r[o];
    __syncthreads();

    long long base = (long long)blockIdx.x * (256LL * 9);
    long long lim  = (long long)E * 9;
#pragma unroll
    for (int it = 0; it < 9; it++) {
        int i = it * 256 + threadIdx.x;
        long long g = base + i;
        if (g < lim) out[g] = sbuf[i];
    }
}

extern "C" void kernel_launch(void* const* d_in, const int* in_sizes, int n_in,
                              void* d_out, int out_size) {
    // metadata order: x [N,32] f32, edge_index [2,E] i32, node_types [N] i32, W [9,72] f32
    const float* x  = (const float*)d_in[0];
    const int*   ei = (const int*)d_in[1];
    const int*   nt = (const int*)d_in[2];
    const float* W  = (const float*)d_in[3];
    float* out = (float*)d_out;

    int N = in_sizes[2];
    int E = in_sizes[1] / 2;

    node_precompute<<<(N + 255) / 256, 256>>>(x, nt, W, N);
    edge_kernel<<<(E + 255) / 256, 256>>>(ei, out, E);
}

// round 4
// speedup vs baseline: 1.3540x; 1.3540x over previous
#include <cuda_runtime.h>
#include <cuda_fp16.h>
#include <cstdint>

#define MAXN 131072
// fp16 tables: row = 16 halves (32 B) per node; values 0..8 used. One 32B sector per row.
// Stored as uint (half2 pairs), stride 8 uints per row.
__device__ unsigned int g_Y[MAXN * 8];
__device__ unsigned int g_Z[MAXN * 8];

__device__ __forceinline__ float fast_tanh(float x) {
    float y;
    asm("tanh.approx.f32 %0, %1;" : "=f"(y) : "f"(x));
    return y;
}

__device__ __forceinline__ unsigned int pack_h2(float a, float b) {
    union { __half2 h; unsigned int u; } cvt;
    cvt.h = __floats2half2_rn(a, b);
    return cvt.u;
}

__device__ __forceinline__ float2 unpack_h2(unsigned int u) {
    union { unsigned int u; __half2 h; } cvt;
    cvt.u = u;
    return __half22float2(cvt.h);
}

// ---------------------------------------------------------------------------
// Kernel 1: per-node precompute of Y (src half of W) and Z (dst half of W),
// with one-hot node-type bias folded in; result rounded to fp16.
//   Y[n][o] = sum_d x[n][d]*W[o][d]    + W[o][64 + t[n]]
//   Z[n][o] = sum_d x[n][d]*W[o][32+d] + W[o][68 + t[n]]
// ---------------------------------------------------------------------------
__global__ void __launch_bounds__(256)
node_precompute(const float* __restrict__ x,
                const int* __restrict__ node_types,
                const float* __restrict__ W,
                int N) {
    __shared__ float sW[9 * 72];
    for (int i = threadIdx.x; i < 9 * 72; i += blockDim.x) sW[i] = W[i];
    __syncthreads();

    int n = blockIdx.x * blockDim.x + threadIdx.x;
    if (n >= N) return;

    float xr[32];
    const float4* xp = reinterpret_cast<const float4*>(x + (size_t)n * 32);
#pragma unroll
    for (int i = 0; i < 8; i++) {
        float4 v = xp[i];
        xr[4 * i + 0] = v.x; xr[4 * i + 1] = v.y;
        xr[4 * i + 2] = v.z; xr[4 * i + 3] = v.w;
    }

    int t = node_types[n];

    float yv[9], zv[9];
#pragma unroll
    for (int o = 0; o < 9; o++) {
        const float* wrow = sW + o * 72;
        float accY = wrow[64 + t];
        float accZ = wrow[68 + t];
#pragma unroll
        for (int d = 0; d < 32; d++) {
            accY = fmaf(xr[d], wrow[d],      accY);
            accZ = fmaf(xr[d], wrow[32 + d], accZ);
        }
        yv[o] = accY;
        zv[o] = accZ;
    }

    // Pack to fp16: h0..h7 as uint4, (h8, 0) as uint
    uint4 ymain, zmain;
    ymain.x = pack_h2(yv[0], yv[1]);
    ymain.y = pack_h2(yv[2], yv[3]);
    ymain.z = pack_h2(yv[4], yv[5]);
    ymain.w = pack_h2(yv[6], yv[7]);
    unsigned int ytail = pack_h2(yv[8], 0.0f);
    zmain.x = pack_h2(zv[0], zv[1]);
    zmain.y = pack_h2(zv[2], zv[3]);
    zmain.z = pack_h2(zv[4], zv[5]);
    zmain.w = pack_h2(zv[6], zv[7]);
    unsigned int ztail = pack_h2(zv[8], 0.0f);

    *reinterpret_cast<uint4*>(g_Y + (size_t)n * 8) = ymain;
    g_Y[(size_t)n * 8 + 4] = ytail;
    *reinterpret_cast<uint4*>(g_Z + (size_t)n * 8) = zmain;
    g_Z[(size_t)n * 8 + 4] = ztail;
}

// ---------------------------------------------------------------------------
// Kernel 2: per-edge: out[e][o] = tanh(Y[src][o] + Z[dst][o])
// Per edge: 2x (LDG.128 + LDG.32) scattered gathers, each row = ONE 32B sector.
// Output staged through smem -> STG.128 coalesced stores.
// ---------------------------------------------------------------------------
__global__ void __launch_bounds__(256)
edge_kernel(const int* __restrict__ ei,
            float* __restrict__ out,
            int E) {
    __shared__ __align__(16) float sbuf[256 * 9];

    int e = blockIdx.x * 256 + threadIdx.x;

    float r[9];
    if (e < E) {
        int s = ei[e];
        int d = ei[E + e];

        uint4 ym = __ldg(reinterpret_cast<const uint4*>(g_Y + (size_t)s * 8));
        unsigned int yt = __ldg(g_Y + (size_t)s * 8 + 4);
        uint4 zm = __ldg(reinterpret_cast<const uint4*>(g_Z + (size_t)d * 8));
        unsigned int zt = __ldg(g_Z + (size_t)d * 8 + 4);

        float2 y01 = unpack_h2(ym.x);
        float2 y23 = unpack_h2(ym.y);
        float2 y45 = unpack_h2(ym.z);
        float2 y67 = unpack_h2(ym.w);
        float  y8  = unpack_h2(yt).x;
        float2 z01 = unpack_h2(zm.x);
        float2 z23 = unpack_h2(zm.y);
        float2 z45 = unpack_h2(zm.z);
        float2 z67 = unpack_h2(zm.w);
        float  z8  = unpack_h2(zt).x;

        r[0] = fast_tanh(y01.x + z01.x);
        r[1] = fast_tanh(y01.y + z01.y);
        r[2] = fast_tanh(y23.x + z23.x);
        r[3] = fast_tanh(y23.y + z23.y);
        r[4] = fast_tanh(y45.x + z45.x);
        r[5] = fast_tanh(y45.y + z45.y);
        r[6] = fast_tanh(y67.x + z67.x);
        r[7] = fast_tanh(y67.y + z67.y);
        r[8] = fast_tanh(y8 + z8);
    } else {
#pragma unroll
        for (int o = 0; o < 9; o++) r[o] = 0.0f;
    }

    // stage: stride 9 across threads -> 9 coprime to 32 -> conflict-free
#pragma unroll
    for (int o = 0; o < 9; o++) sbuf[threadIdx.x * 9 + o] = r[o];
    __syncthreads();

    // vectorized coalesced stores: 576 float4 per block
    const long long lim  = (long long)E * 9;
    const long long lim4 = lim >> 2;              // floor(E*9/4)
    const float4* sb4 = reinterpret_cast<const float4*>(sbuf);
    float4* out4 = reinterpret_cast<float4*>(out);
    long long base4 = (long long)blockIdx.x * 576;
#pragma unroll
    for (int it = 0; it < 3; it++) {
        int i = it * 256 + threadIdx.x;
        if (i < 576) {
            long long g = base4 + i;
            if (g < lim4) out4[g] = sb4[i];
        }
    }
    // scalar tail (E*9 not divisible by 4): at most 3 elements
    long long tstart = lim4 << 2;
    long long gbase  = (long long)blockIdx.x * 2304;
    if (threadIdx.x < 4) {
        long long g = tstart + threadIdx.x;
        if (g < lim && g >= gbase && g < gbase + 2304)
            out[g] = sbuf[(int)(g - gbase)];
    }
}

extern "C" void kernel_launch(void* const* d_in, const int* in_sizes, int n_in,
                              void* d_out, int out_size) {
    // metadata order: x [N,32] f32, edge_index [2,E] i32, node_types [N] i32, W [9,72] f32
    const float* x  = (const float*)d_in[0];
    const int*   ei = (const int*)d_in[1];
    const int*   nt = (const int*)d_in[2];
    const float* W  = (const float*)d_in[3];
    float* out = (float*)d_out;

    int N = in_sizes[2];
    int E = in_sizes[1] / 2;

    node_precompute<<<(N + 255) / 256, 256>>>(x, nt, W, N);
    edge_kernel<<<(E + 255) / 256, 256>>>(ei, out, E);
}

// round 5
// speedup vs baseline: 1.5099x; 1.1151x over previous
#include <cuda_runtime.h>
#include <cuda_fp16.h>
#include <cstdint>

#define MAXN 131072
// Packed tables: one uint4 (16B) per node per table.
// Layout (12-bit unsigned q values, bias 2048; fp16 row scale):
//  w0: q0[0:12) q1[12:24) q2lo[24:32)
//  w1: q2hi[0:4) q3[4:16) q4[16:28) q5lo[28:32)
//  w2: q5hi[0:8) q6[8:20) q7[20:32)
//  w3: q8[0:12) pad[12:16) scale_fp16[16:32)
__device__ uint4 g_Y[MAXN];
__device__ uint4 g_Z[MAXN];

__device__ __forceinline__ float fast_tanh(float x) {
    float y;
    asm("tanh.approx.f32 %0, %1;" : "=f"(y) : "f"(x));
    return y;
}

// ---------------------------------------------------------------------------
// Kernel 1: per-node precompute + 12-bit shared-scale quantization.
//   Y[n][o] = sum_d x[n][d]*W[o][d]    + W[o][64 + t[n]]
//   Z[n][o] = sum_d x[n][d]*W[o][32+d] + W[o][68 + t[n]]
// ---------------------------------------------------------------------------
__device__ __forceinline__ uint4 pack_row(const float* v) {
    float mx = fabsf(v[0]);
#pragma unroll
    for (int o = 1; o < 9; o++) mx = fmaxf(mx, fabsf(v[o]));
    // stored scale (fp16); quantize against the STORED value so its rounding
    // is absorbed (no systematic scale error)
    __half hs = __float2half_rn(fmaxf(mx, 1e-20f) * (1.0f / 2047.0f));
    float s = __half2float(hs);
    float inv = 1.0f / s;

    unsigned int q[9];
#pragma unroll
    for (int o = 0; o < 9; o++) {
        int qi = __float2int_rn(v[o] * inv);
        qi = max(-2047, min(2047, qi));
        q[o] = (unsigned int)(qi + 2048);
    }
    uint4 w;
    w.x = q[0] | (q[1] << 12) | (q[2] << 24);
    w.y = (q[2] >> 8) | (q[3] << 4) | (q[4] << 16) | (q[5] << 28);
    w.z = (q[5] >> 4) | (q[6] << 8) | (q[7] << 20);
    w.w = q[8] | ((unsigned int)__half_as_ushort(hs) << 16);
    return w;
}

__global__ void __launch_bounds__(256)
node_precompute(const float* __restrict__ x,
                const int* __restrict__ node_types,
                const float* __restrict__ W,
                int N) {
    __shared__ float sW[9 * 72];
    for (int i = threadIdx.x; i < 9 * 72; i += blockDim.x) sW[i] = W[i];
    __syncthreads();

    int n = blockIdx.x * blockDim.x + threadIdx.x;
    if (n >= N) return;

    float xr[32];
    const float4* xp = reinterpret_cast<const float4*>(x + (size_t)n * 32);
#pragma unroll
    for (int i = 0; i < 8; i++) {
        float4 v = xp[i];
        xr[4 * i + 0] = v.x; xr[4 * i + 1] = v.y;
        xr[4 * i + 2] = v.z; xr[4 * i + 3] = v.w;
    }

    int t = node_types[n];

    float yv[9], zv[9];
#pragma unroll
    for (int o = 0; o < 9; o++) {
        const float* wrow = sW + o * 72;
        float accY = wrow[64 + t];
        float accZ = wrow[68 + t];
#pragma unroll
        for (int d = 0; d < 32; d++) {
            accY = fmaf(xr[d], wrow[d],      accY);
            accZ = fmaf(xr[d], wrow[32 + d], accZ);
        }
        yv[o] = accY;
        zv[o] = accZ;
    }

    g_Y[n] = pack_row(yv);
    g_Z[n] = pack_row(zv);
}

// ---------------------------------------------------------------------------
// Decode helpers: constant-shift 12-bit extracts (1-2 SASS ops each)
// ---------------------------------------------------------------------------
__device__ __forceinline__ void unpack_row(uint4 w, float q[9], float& s) {
    q[0] = (float)( w.x        & 0xFFFu);
    q[1] = (float)((w.x >> 12) & 0xFFFu);
    q[2] = (float)(((w.x >> 24) | (w.y << 8)) & 0xFFFu);
    q[3] = (float)((w.y >> 4)  & 0xFFFu);
    q[4] = (float)((w.y >> 16) & 0xFFFu);
    q[5] = (float)(((w.y >> 28) | (w.z << 4)) & 0xFFFu);
    q[6] = (float)((w.z >> 8)  & 0xFFFu);
    q[7] = (float)( w.z >> 20);
    q[8] = (float)( w.w        & 0xFFFu);
    s = __half2float(__ushort_as_half((unsigned short)(w.w >> 16)));
}

// ---------------------------------------------------------------------------
// Kernel 2: per-edge: out[e][o] = tanh(sy*qy[o] + sz*qz[o] + c),
//           c = -2048*(sy+sz).  Exactly 2 scattered LDG.128 per edge.
// Output staged through smem -> STG.128 coalesced stores.
// ---------------------------------------------------------------------------
__global__ void __launch_bounds__(256)
edge_kernel(const int* __restrict__ ei,
            float* __restrict__ out,
            int E) {
    __shared__ __align__(16) float sbuf[256 * 9];

    int e = blockIdx.x * 256 + threadIdx.x;

    float r[9];
    if (e < E) {
        int s = ei[e];
        int d = ei[E + e];

        uint4 yw = __ldg(&g_Y[s]);
        uint4 zw = __ldg(&g_Z[d]);

        float qy[9], qz[9], sy, sz;
        unpack_row(yw, qy, sy);
        unpack_row(zw, qz, sz);
        float c = -2048.0f * (sy + sz);

#pragma unroll
        for (int o = 0; o < 9; o++)
            r[o] = fast_tanh(fmaf(sy, qy[o], fmaf(sz, qz[o], c)));
    } else {
#pragma unroll
        for (int o = 0; o < 9; o++) r[o] = 0.0f;
    }

    // stage: stride 9 across threads -> 9 coprime to 32 -> conflict-free
#pragma unroll
    for (int o = 0; o < 9; o++) sbuf[threadIdx.x * 9 + o] = r[o];
    __syncthreads();

    // vectorized coalesced stores: 576 float4 per block
    const long long lim  = (long long)E * 9;
    const long long lim4 = lim >> 2;              // floor(E*9/4)
    const float4* sb4 = reinterpret_cast<const float4*>(sbuf);
    float4* out4 = reinterpret_cast<float4*>(out);
    long long base4 = (long long)blockIdx.x * 576;
#pragma unroll
    for (int it = 0; it < 3; it++) {
        int i = it * 256 + threadIdx.x;
        if (i < 576) {
            long long g = base4 + i;
            if (g < lim4) out4[g] = sb4[i];
        }
    }
    // scalar tail (E*9 not divisible by 4): at most 3 elements
    long long tstart = lim4 << 2;
    long long gbase  = (long long)blockIdx.x * 2304;
    if (threadIdx.x < 4) {
        long long g = tstart + threadIdx.x;
        if (g < lim && g >= gbase && g < gbase + 2304)
            out[g] = sbuf[(int)(g - gbase)];
    }
}

extern "C" void kernel_launch(void* const* d_in, const int* in_sizes, int n_in,
                              void* d_out, int out_size) {
    // metadata order: x [N,32] f32, edge_index [2,E] i32, node_types [N] i32, W [9,72] f32
    const float* x  = (const float*)d_in[0];
    const int*   ei = (const int*)d_in[1];
    const int*   nt = (const int*)d_in[2];
    const float* W  = (const float*)d_in[3];
    float* out = (float*)d_out;

    int N = in_sizes[2];
    int E = in_sizes[1] / 2;

    node_precompute<<<(N + 255) / 256, 256>>>(x, nt, W, N);
    edge_kernel<<<(E + 255) / 256, 256>>>(ei, out, E);
}

// round 6
// speedup vs baseline: 1.5208x; 1.0072x over previous
#include <cuda_runtime.h>
#include <cuda_fp16.h>
#include <cstdint>

#define MAXN 131072
// Packed tables: one uint4 (16B) per node per table.
// 12-bit unsigned q values (bias 2048) + fp16 row scale.
__device__ uint4 g_Y[MAXN];
__device__ uint4 g_Z[MAXN];

__device__ __forceinline__ float fast_tanh(float x) {
    float y;
    asm("tanh.approx.f32 %0, %1;" : "=f"(y) : "f"(x));
    return y;
}

__device__ __forceinline__ uint4 pack_row(const float* v) {
    float mx = fabsf(v[0]);
#pragma unroll
    for (int o = 1; o < 9; o++) mx = fmaxf(mx, fabsf(v[o]));
    // quantize against the STORED (fp16-rounded) scale: no systematic scale error
    __half hs = __float2half_rn(fmaxf(mx, 1e-20f) * (1.0f / 2047.0f));
    float inv = 1.0f / __half2float(hs);

    unsigned int q[9];
#pragma unroll
    for (int o = 0; o < 9; o++) {
        int qi = __float2int_rn(v[o] * inv);
        qi = max(-2047, min(2047, qi));
        q[o] = (unsigned int)(qi + 2048);
    }
    uint4 w;
    w.x = q[0] | (q[1] << 12) | (q[2] << 24);
    w.y = (q[2] >> 8) | (q[3] << 4) | (q[4] << 16) | (q[5] << 28);
    w.z = (q[5] >> 4) | (q[6] << 8) | (q[7] << 20);
    w.w = q[8] | ((unsigned int)__half_as_ushort(hs) << 16);
    return w;
}

// ---------------------------------------------------------------------------
// Kernel 1: per-node precompute + 12-bit quantization.
// Weight fetches vectorized: LDS.128 only (144/thread vs 576 scalar LDS).
// ---------------------------------------------------------------------------
__global__ void __launch_bounds__(256)
node_precompute(const float* __restrict__ x,
                const int* __restrict__ node_types,
                const float* __restrict__ W,
                int N) {
    __shared__ __align__(16) float sW[9 * 72];
    for (int i = threadIdx.x; i < 9 * 72; i += blockDim.x) sW[i] = W[i];
    __syncthreads();

    int n = blockIdx.x * blockDim.x + threadIdx.x;
    if (n >= N) return;

    float4 xr[8];
    const float4* xp = reinterpret_cast<const float4*>(x + (size_t)n * 32);
#pragma unroll
    for (int i = 0; i < 8; i++) xr[i] = xp[i];

    int t = node_types[n];

    float yv[9], zv[9];
#pragma unroll
    for (int o = 0; o < 9; o++) {
        const float4* w4 = reinterpret_cast<const float4*>(sW + o * 72);
        float accY = sW[o * 72 + 64 + t];
        float accZ = sW[o * 72 + 68 + t];
#pragma unroll
        for (int i = 0; i < 8; i++) {
            float4 wa = w4[i];       // wrow[4i..4i+3]
            float4 wb = w4[8 + i];   // wrow[32+4i..]
            accY = fmaf(xr[i].x, wa.x, accY);
            accY = fmaf(xr[i].y, wa.y, accY);
            accY = fmaf(xr[i].z, wa.z, accY);
            accY = fmaf(xr[i].w, wa.w, accY);
            accZ = fmaf(xr[i].x, wb.x, accZ);
            accZ = fmaf(xr[i].y, wb.y, accZ);
            accZ = fmaf(xr[i].z, wb.z, accZ);
            accZ = fmaf(xr[i].w, wb.w, accZ);
        }
        yv[o] = accY;
        zv[o] = accZ;
    }

    g_Y[n] = pack_row(yv);
    g_Z[n] = pack_row(zv);
}

__device__ __forceinline__ void unpack_row(uint4 w, float q[9], float& s) {
    q[0] = (float)( w.x        & 0xFFFu);
    q[1] = (float)((w.x >> 12) & 0xFFFu);
    q[2] = (float)(((w.x >> 24) | (w.y << 8)) & 0xFFFu);
    q[3] = (float)((w.y >> 4)  & 0xFFFu);
    q[4] = (float)((w.y >> 16) & 0xFFFu);
    q[5] = (float)(((w.y >> 28) | (w.z << 4)) & 0xFFFu);
    q[6] = (float)((w.z >> 8)  & 0xFFFu);
    q[7] = (float)( w.z >> 20);
    q[8] = (float)( w.w        & 0xFFFu);
    s = __half2float(__ushort_as_half((unsigned short)(w.w >> 16)));
}

__device__ __forceinline__ void decode_edge(uint4 yw, uint4 zw, float* r) {
    float qy[9], qz[9], sy, sz;
    unpack_row(yw, qy, sy);
    unpack_row(zw, qz, sz);
    float c = -2048.0f * (sy + sz);
#pragma unroll
    for (int o = 0; o < 9; o++)
        r[o] = fast_tanh(fmaf(sy, qy[o], fmaf(sz, qz[o], c)));
}

// ---------------------------------------------------------------------------
// Kernel 2: 2 edges per thread; 4 scattered LDG.128 issued up front.
// Scalar smem staging (conflict-free) + scalar coalesced STG.
// ---------------------------------------------------------------------------
#define EPB 512   // edges per block (256 threads x 2)

__global__ void __launch_bounds__(256)
edge_kernel(const int* __restrict__ ei,
            float* __restrict__ out,
            int E) {
    __shared__ float sbuf[EPB * 9];

    int t  = blockIdx.x * 256 + threadIdx.x;   // pair index
    int e0 = 2 * t;

    uint4 y0, y1, z0, z1;
    bool v0 = (e0 < E), v1 = (e0 + 1 < E);

    if (v1) {
        // full pair: vector index loads (E even => ei+E is 8B aligned when E even;
        // guarded by v1 path only being hit with in-bounds pair)
        int2 sp, dp;
        if ((E & 1) == 0) {
            sp = reinterpret_cast<const int2*>(ei)[t];
            dp = reinterpret_cast<const int2*>(ei + E)[t];
        } else {
            sp = make_int2(ei[e0], ei[e0 + 1]);
            dp = make_int2(ei[E + e0], ei[E + e0 + 1]);
        }
        y0 = __ldg(&g_Y[sp.x]);
        z0 = __ldg(&g_Z[dp.x]);
        y1 = __ldg(&g_Y[sp.y]);
        z1 = __ldg(&g_Z[dp.y]);
    } else if (v0) {
        int s0 = ei[e0], d0 = ei[E + e0];
        y0 = __ldg(&g_Y[s0]);
        z0 = __ldg(&g_Z[d0]);
        y1 = make_uint4(0, 0, 0, 0);
        z1 = make_uint4(0, 0, 0, 0);
    } else {
        y0 = y1 = z0 = z1 = make_uint4(0, 0, 0, 0);
    }

    float r0[9], r1[9];
    decode_edge(y0, z0, r0);
    decode_edge(y1, z1, r1);

    int le = 2 * threadIdx.x;   // local edge id
#pragma unroll
    for (int o = 0; o < 9; o++) sbuf[le * 9 + o]       = r0[o];
#pragma unroll
    for (int o = 0; o < 9; o++) sbuf[(le + 1) * 9 + o] = r1[o];
    __syncthreads();

    // scalar coalesced stores: EPB*9 = 4608 floats per block, 18 iters
    long long gbase = (long long)blockIdx.x * (EPB * 9);
    long long lim   = (long long)E * 9;
#pragma unroll
    for (int it = 0; it < 18; it++) {
        int i = it * 256 + threadIdx.x;
        long long g = gbase + i;
        if (g < lim) out[g] = sbuf[i];
    }
}

extern "C" void kernel_launch(void* const* d_in, const int* in_sizes, int n_in,
                              void* d_out, int out_size) {
    // metadata order: x [N,32] f32, edge_index [2,E] i32, node_types [N] i32, W [9,72] f32
    const float* x  = (const float*)d_in[0];
    const int*   ei = (const int*)d_in[1];
    const int*   nt = (const int*)d_in[2];
    const float* W  = (const float*)d_in[3];
    float* out = (float*)d_out;

    int N = in_sizes[2];
    int E = in_sizes[1] / 2;

    node_precompute<<<(N + 255) / 256, 256>>>(x, nt, W, N);
    edge_kernel<<<(E + EPB - 1) / EPB, 256>>>(ei, out, E);
}

// round 7
// speedup vs baseline: 1.5619x; 1.0270x over previous
#include <cuda_runtime.h>
#include <cuda_fp16.h>
#include <cstdint>

#define MAXN 131072
// Packed tables: one uint4 (16B) per node per table.
// 12-bit unsigned q values (bias 2048) + fp16 row scale.
__device__ uint4 g_Y[MAXN];
__device__ uint4 g_Z[MAXN];

__device__ __forceinline__ uint4 pack_row(const float* v) {
    float mx = fabsf(v[0]);
#pragma unroll
    for (int o = 1; o < 9; o++) mx = fmaxf(mx, fabsf(v[o]));
    // quantize against the STORED (fp16-rounded) scale: no systematic scale error
    __half hs = __float2half_rn(fmaxf(mx, 1e-20f) * (1.0f / 2047.0f));
    float inv = 1.0f / __half2float(hs);

    unsigned int q[9];
#pragma unroll
    for (int o = 0; o < 9; o++) {
        int qi = __float2int_rn(v[o] * inv);
        qi = max(-2047, min(2047, qi));
        q[o] = (unsigned int)(qi + 2048);
    }
    uint4 w;
    w.x = q[0] | (q[1] << 12) | (q[2] << 24);
    w.y = (q[2] >> 8) | (q[3] << 4) | (q[4] << 16) | (q[5] << 28);
    w.z = (q[5] >> 4) | (q[6] << 8) | (q[7] << 20);
    w.w = q[8] | ((unsigned int)__half_as_ushort(hs) << 16);
    return w;
}

// ---------------------------------------------------------------------------
// Kernel 1: per-node precompute + 12-bit quantization.
// x rows staged through smem: coalesced LDG.128, stride-36 rows so the
// per-thread LDS.128 reads are bank-conflict-free.
// ---------------------------------------------------------------------------
__global__ void __launch_bounds__(256)
node_precompute(const float* __restrict__ x,
                const int* __restrict__ node_types,
                const float* __restrict__ W,
                int N) {
    __shared__ __align__(16) float sW[9 * 72];
    __shared__ __align__(16) float xs[256 * 36];

    for (int i = threadIdx.x; i < 9 * 72; i += blockDim.x) sW[i] = W[i];

    int base = blockIdx.x * 256;
    // cooperative coalesced load of 256 x-rows (float4 granularity)
    const float4* xp = reinterpret_cast<const float4*>(x);
#pragma unroll
    for (int i = 0; i < 8; i++) {
        int lin = i * 256 + threadIdx.x;      // 0..2047 float4s
        int nl  = lin >> 3;                   // local node
        int cp  = lin & 7;                    // float4 within row
        if (base + nl < N) {
            float4 v = xp[(size_t)(base + nl) * 8 + cp];
            *reinterpret_cast<float4*>(xs + nl * 36 + cp * 4) = v;
        }
    }
    __syncthreads();

    int n = base + threadIdx.x;
    if (n >= N) return;

    float4 xr[8];
    const float4* myrow = reinterpret_cast<const float4*>(xs + threadIdx.x * 36);
#pragma unroll
    for (int i = 0; i < 8; i++) xr[i] = myrow[i];

    int t = node_types[n];

    float yv[9], zv[9];
#pragma unroll
    for (int o = 0; o < 9; o++) {
        const float4* w4 = reinterpret_cast<const float4*>(sW + o * 72);
        float accY = sW[o * 72 + 64 + t];
        float accZ = sW[o * 72 + 68 + t];
#pragma unroll
        for (int i = 0; i < 8; i++) {
            float4 wa = w4[i];
            float4 wb = w4[8 + i];
            accY = fmaf(xr[i].x, wa.x, accY);
            accY = fmaf(xr[i].y, wa.y, accY);
            accY = fmaf(xr[i].z, wa.z, accY);
            accY = fmaf(xr[i].w, wa.w, accY);
            accZ = fmaf(xr[i].x, wb.x, accZ);
            accZ = fmaf(xr[i].y, wb.y, accZ);
            accZ = fmaf(xr[i].z, wb.z, accZ);
            accZ = fmaf(xr[i].w, wb.w, accZ);
        }
        yv[o] = accY;
        zv[o] = accZ;
    }

    g_Y[n] = pack_row(yv);
    g_Z[n] = pack_row(zv);
}

__device__ __forceinline__ void unpack_row(uint4 w, float q[9], float& s) {
    q[0] = (float)( w.x        & 0xFFFu);
    q[1] = (float)((w.x >> 12) & 0xFFFu);
    q[2] = (float)(((w.x >> 24) | (w.y << 8)) & 0xFFFu);
    q[3] = (float)((w.y >> 4)  & 0xFFFu);
    q[4] = (float)((w.y >> 16) & 0xFFFu);
    q[5] = (float)(((w.y >> 28) | (w.z << 4)) & 0xFFFu);
    q[6] = (float)((w.z >> 8)  & 0xFFFu);
    q[7] = (float)( w.z >> 20);
    q[8] = (float)( w.w        & 0xFFFu);
    s = __half2float(__ushort_as_half((unsigned short)(w.w >> 16)));
}

// sums only (no activation)
__device__ __forceinline__ void decode_edge_sum(uint4 yw, uint4 zw, float* a) {
    float qy[9], qz[9], sy, sz;
    unpack_row(yw, qy, sy);
    unpack_row(zw, qz, sz);
    float c = -2048.0f * (sy + sz);
#pragma unroll
    for (int o = 0; o < 9; o++)
        a[o] = fmaf(sy, qy[o], fmaf(sz, qz[o], c));
}

__device__ __forceinline__ unsigned int tanh_h2(float lo, float hi) {
    __half2 h = __floats2half2_rn(lo, hi);
    unsigned int u;
    {
        union { __half2 h; unsigned int u; } cvt; cvt.h = h; u = cvt.u;
    }
    asm("tanh.approx.f16x2 %0, %0;" : "+r"(u));
    return u;
}

// ---------------------------------------------------------------------------
// Kernel 2: 2 edges/thread; 4 scattered LDG.128 up front; fp32 sums packed to
// half2, SIMD tanh (halves MUFU), half2 smem staging, coalesced STG.64 out.
// ---------------------------------------------------------------------------
#define EPB 512   // edges per block (256 threads x 2)

__global__ void __launch_bounds__(256)
edge_kernel(const int* __restrict__ ei,
            float* __restrict__ out,
            int E) {
    __shared__ unsigned int sbuf[EPB * 9 / 2];   // 2304 half2 = 9216 B

    int t  = blockIdx.x * 256 + threadIdx.x;   // pair index
    int e0 = 2 * t;

    uint4 y0, y1, z0, z1;
    bool v0 = (e0 < E), v1 = (e0 + 1 < E);

    if (v1) {
        int2 sp, dp;
        if ((E & 1) == 0) {
            sp = reinterpret_cast<const int2*>(ei)[t];
            dp = reinterpret_cast<const int2*>(ei + E)[t];
        } else {
            sp = make_int2(ei[e0], ei[e0 + 1]);
            dp = make_int2(ei[E + e0], ei[E + e0 + 1]);
        }
        y0 = __ldg(&g_Y[sp.x]);
        z0 = __ldg(&g_Z[dp.x]);
        y1 = __ldg(&g_Y[sp.y]);
        z1 = __ldg(&g_Z[dp.y]);
    } else if (v0) {
        int s0 = ei[e0], d0 = ei[E + e0];
        y0 = __ldg(&g_Y[s0]);
        z0 = __ldg(&g_Z[d0]);
        y1 = make_uint4(0, 0, 0, 0);
        z1 = make_uint4(0, 0, 0, 0);
    } else {
        y0 = y1 = z0 = z1 = make_uint4(0, 0, 0, 0);
    }

    float a[18];
    decode_edge_sum(y0, z0, a);
    decode_edge_sum(y1, z1, a + 9);

    // 18 results -> 9 half2 with SIMD tanh; stride-9 STS (9 coprime 32 -> no conflicts)
#pragma unroll
    for (int k = 0; k < 9; k++)
        sbuf[threadIdx.x * 9 + k] = tanh_h2(a[2 * k], a[2 * k + 1]);
    __syncthreads();

    // coalesced output: 2304 half2 per block -> float2 stores
    long long lim   = (long long)E * 9;                 // total floats
    long long g2base = (long long)blockIdx.x * 2304;    // half2 index base
#pragma unroll
    for (int it = 0; it < 9; it++) {
        int i = it * 256 + threadIdx.x;                 // 0..2303
        long long g2 = g2base + i;
        long long f0 = 2 * g2;
        if (f0 + 1 < lim) {
            union { unsigned int u; __half2 h; } cvt; cvt.u = sbuf[i];
            float2 f = __half22float2(cvt.h);
            reinterpret_cast<float2*>(out)[g2] = f;
        } else if (f0 < lim) {
            union { unsigned int u; __half2 h; } cvt; cvt.u = sbuf[i];
            out[f0] = __low2float(cvt.h);
        }
    }
}

extern "C" void kernel_launch(void* const* d_in, const int* in_sizes, int n_in,
                              void* d_out, int out_size) {
    // metadata order: x [N,32] f32, edge_index [2,E] i32, node_types [N] i32, W [9,72] f32
    const float* x  = (const float*)d_in[0];
    const int*   ei = (const int*)d_in[1];
    const int*   nt = (const int*)d_in[2];
    const float* W  = (const float*)d_in[3];
    float* out = (float*)d_out;

    int N = in_sizes[2];
    int E = in_sizes[1] / 2;

    node_precompute<<<(N + 255) / 256, 256>>>(x, nt, W, N);
    edge_kernel<<<(E + EPB - 1) / EPB, 256>>>(ei, out, E);
}